// round 12
// baseline (speedup 1.0000x reference)
#include <cuda_runtime.h>
#include <cuda_fp16.h>
#include <math.h>

#define HW      16384
#define KJ      300
#define NLINES  49152
#define NBMW    2816            // 2816*32 = 90112 >= 90000 bits
#define MPAD    44928           // ceil(44850/128)*128
#define PI_F    3.14159265358979323846f

// ---------------- scratch (static device memory; no allocations) ----------------
__device__ int                 g_count;
__device__ float               g_junc[2 * KJ];
__device__ unsigned int        g_bitmap[NBMW];
__device__ __align__(128) __half g_loi[(size_t)HW * 128];      // [pixel][channel] fp16
__device__ __align__(128) __half g_bufA[(size_t)MPAD * 1024];  // feats (fp16)
__device__ __align__(128) __half g_bufB[(size_t)MPAD * 1024];  // h1 (fp16)
__device__ __align__(128) __half g_w1h[1024 * 1024];
__device__ __align__(128) __half g_w2h[1024 * 1024];
__device__ __align__(128) float  g_part[(size_t)MPAD * 32];    // fused-final partials

__device__ __forceinline__ float sigm(float x) { return 1.0f / (1.0f + expf(-x)); }

__device__ __forceinline__ void cp16(void* smem, const void* gptr) {
    unsigned s = (unsigned)__cvta_generic_to_shared(smem);
    asm volatile("cp.async.cg.shared.global [%0], [%1], 16;" :: "r"(s), "l"(gptr));
}
__device__ __forceinline__ void cp_commit() { asm volatile("cp.async.commit_group;"); }
__device__ __forceinline__ void cp_wait1()  { asm volatile("cp.async.wait_group 1;"); }

// ---------------- stage 0 (side stream): fp16 weight conversion ----------------
__global__ void k_cvt(const float* __restrict__ w1, const float* __restrict__ w2) {
    int i = blockIdx.x * blockDim.x + threadIdx.x;   // 0 .. 1M-1
    g_w1h[i] = __float2half(w1[i]);
    g_w2h[i] = __float2half(w2[i]);
}

// ---------------- stage 1 (fused): jloc + NMS + candidates + select + sort + coords ----
// dynamic smem layout: [0,64K) jloc floats -> later {hist u32[8192] | sbuf u64[4096]}
//                      [64K,96K) cand u64[4096]
__global__ void k_front(const float* __restrict__ heat) {
    extern __shared__ char dyn[];
    float* jloc = (float*)dyn;
    unsigned int* hist = (unsigned int*)dyn;                          // aliases jloc[0:8192]
    unsigned long long* sbuf = (unsigned long long*)(dyn + 32768);    // aliases jloc[8192:16384]
    unsigned long long* cand = (unsigned long long*)(dyn + 65536);
    __shared__ int wtot[32];
    __shared__ int sCnt, sB, sTot, sPos, sAll;
    int t = threadIdx.x;
    int lane = t & 31, wid = t >> 5;
    if (t == 0) { sCnt = 0; sPos = 0; sB = 0; sTot = 0; sAll = 0; }

    // jloc = softmax(ch5,ch6)[1]
    #pragma unroll
    for (int q = 0; q < 16; q++) {
        int i = q * 1024 + t;
        jloc[i] = 1.0f / (1.0f + expf(heat[5 * HW + i] - heat[6 * HW + i]));
    }
    __syncthreads();

    // 3x3 NMS + gather candidates
    #pragma unroll
    for (int q = 0; q < 16; q++) {
        int i = q * 1024 + t;
        int y = i >> 7, x = i & 127;
        float v = jloc[i];
        float m = v;
        for (int dy = -1; dy <= 1; dy++) {
            int yy = y + dy; if ((unsigned)yy >= 128u) continue;
            for (int dx = -1; dx <= 1; dx++) {
                if (dy == 0 && dx == 0) continue;
                int xx = x + dx; if ((unsigned)xx >= 128u) continue;
                m = fmaxf(m, jloc[yy * 128 + xx]);
            }
        }
        if (v == m && v > 0.0f) {
            int p = atomicAdd(&sCnt, 1);
            if (p < 4096)
                cand[p] = ((unsigned long long)__float_as_uint(v) << 32) |
                          (unsigned long long)(0xFFFFFFFFu - (unsigned)i);
        }
    }
    __syncthreads();
    int cc = min(sCnt, 4096);

    // histogram over top-13 float bits (jloc region now dead)
    #pragma unroll
    for (int q = 0; q < 8; q++) hist[q * 1024 + t] = 0u;
    __syncthreads();
    unsigned long long kk[4];
    #pragma unroll
    for (int q = 0; q < 4; q++) {
        int idx = q * 1024 + t;
        unsigned long long key = (idx < cc) ? cand[idx] : 0ULL;
        kk[q] = key;
        if (key >> 32)
            atomicAdd(&hist[(int)((key >> 50) & 0x1FFF)], 1u);
    }
    __syncthreads();

    // suffix sums via warp shfl (bins descending = scores descending)
    int gs = 0;
    #pragma unroll
    for (int b = 0; b < 8; b++) gs += hist[t * 8 + b];
    int s = gs;
    #pragma unroll
    for (int o = 1; o < 32; o <<= 1) {
        int v = __shfl_down_sync(0xFFFFFFFFu, s, o);
        if (lane + o < 32) s += v;
    }
    if (lane == 0) wtot[wid] = s;
    __syncthreads();
    if (wid == 0) {
        int s2 = wtot[lane];
        #pragma unroll
        for (int o = 1; o < 32; o <<= 1) {
            int v = __shfl_down_sync(0xFFFFFFFFu, s2, o);
            if (lane + o < 32) s2 += v;
        }
        wtot[lane] = s2 - ((lane < 31) ? 0 : 0);   // inclusive suffix of warp totals
        if (lane == 0) sAll = s2;
    }
    __syncthreads();
    int wsufExcl = (wid < 31) ? wtot[wid + 1] : 0;
    int suf = s + wsufExcl;            // count in groups >= t (incl own)
    int sufN = suf - gs;               // count in groups > t
    if (t == 0 && sAll < KJ) { sB = 0; sTot = sAll; }
    if (suf >= KJ && sufN < KJ) {
        int run = sufN;
        for (int b = t * 8 + 7; b >= t * 8; b--) {
            run += hist[b];
            if (run >= KJ) { sB = b; sTot = run; break; }
        }
    }
    __syncthreads();
    int B = sB, total = sTot;

    // collect survivors into sbuf
    #pragma unroll
    for (int q = 0; q < 4; q++) {
        unsigned long long key = kk[q];
        if ((key >> 32) && (int)((key >> 50) & 0x1FFF) >= B) {
            int p = atomicAdd(&sPos, 1);
            sbuf[p] = key;
        }
    }
    __syncthreads();

    int n = (total <= 512) ? 512 : (total <= 1024) ? 1024 : (total <= 2048) ? 2048 : 4096;
    for (int i = total + t; i < n; i += 1024) sbuf[i] = 0ULL;
    __syncthreads();

    for (int k = 2; k <= n; k <<= 1) {
        for (int j = k >> 1; j > 0; j >>= 1) {
            for (int i = t; i < n; i += 1024) {
                int ixj = i ^ j;
                if (ixj > i) {
                    unsigned long long a = sbuf[i], b = sbuf[ixj];
                    bool descSeg = (i & k) == 0;
                    if (descSeg ? (a < b) : (a > b)) { sbuf[i] = b; sbuf[ixj] = a; }
                }
            }
            __syncthreads();
        }
    }

    if (t < KJ) {
        unsigned long long key = sbuf[t];
        float v = __uint_as_float((unsigned)(key >> 32));
        if (v > 0.008f) {
            unsigned pix = 0xFFFFFFFFu - (unsigned)(key & 0xFFFFFFFFu);
            float x = (float)(pix & 127u), y = (float)(pix >> 7);
            g_junc[2 * t + 0] = x + sigm(heat[7 * HW + pix]);
            g_junc[2 * t + 1] = y + sigm(heat[8 * HW + pix]);
        } else {
            g_junc[2 * t + 0] = 1e6f;
            g_junc[2 * t + 1] = 1e6f;
        }
    }
}

// ---------------- stage 3: HAFM decode + matching (1 endpoint/thread) ----------------
__global__ void k_match(const float* __restrict__ heat) {
    __shared__ float sj[2 * KJ];
    for (int i = threadIdx.x; i < 2 * KJ; i += blockDim.x) sj[i] = g_junc[i];
    __syncthreads();
    int gtid = blockIdx.x * blockDim.x + threadIdx.x;
    if (gtid >= 2 * NLINES) return;
    int n = gtid >> 1;
    int e = gtid & 1;
    int ch = n >> 14;
    int pix = n & (HW - 1);
    float x0 = (float)(pix & 127), y0 = (float)(pix >> 7);
    float a0   = sigm(heat[0 * HW + pix]);
    float dist = sigm(heat[3 * HW + pix]);
    float bias = sigm(heat[4 * HW + pix]);
    float d = dist + bias * (float)(ch - 1);
    d = fminf(fmaxf(d, 0.0f), 1.0f);
    float ang0 = (a0 - 0.5f) * PI_F * 2.0f;
    float c0 = cosf(ang0), s0 = sinf(ang0);
    float te;
    if (e == 0) te =  tanf(sigm(heat[1 * HW + pix]) * (PI_F * 0.5f));
    else        te = -tanf(sigm(heat[2 * HW + pix]) * (PI_F * 0.5f));
    float ex = fminf(fmaxf((c0 - s0 * te) * d * 5.0f + x0, 0.0f), 127.0f);
    float ey = fminf(fmaxf((s0 + c0 * te) * d * 5.0f + y0, 0.0f), 127.0f);

    int j = 0;
    float mbest = 3.4e38f;
    const float2* sj2 = (const float2*)sj;
    #pragma unroll 4
    for (int k = 0; k < KJ; k++) {
        float2 jxy = sj2[k];
        float dx = jxy.x - ex, dy = jxy.y - ey;
        float dd = dx * dx + dy * dy;
        if (dd < mbest) { mbest = dd; j = k; }
    }
    int jo = __shfl_xor_sync(0xFFFFFFFFu, j, 1);
    if (e == 0) {
        int lo = min(j, jo), hi = max(j, jo);
        if (lo < hi) {
            int id = lo * KJ + hi;
            atomicOr(&g_bitmap[id >> 5], 1u << (id & 31));
        }
    }
}

// ---------------- stage 4: ordered bitmap compaction (warp-scan) ----------------
__global__ void k_compact(float* __restrict__ dout) {
    __shared__ int wsum[32];
    int tid = threadIdx.x;
    int lane = tid & 31, wid = tid >> 5;
    int base = tid * 3;
    unsigned w[3] = {0u, 0u, 0u};
    int c = 0;
    #pragma unroll
    for (int q = 0; q < 3; q++) {
        int wi = base + q;
        if (wi < NBMW) { w[q] = g_bitmap[wi]; c += __popc(w[q]); }
    }
    int incl = c;
    #pragma unroll
    for (int o = 1; o < 32; o <<= 1) {
        int v = __shfl_up_sync(0xFFFFFFFFu, incl, o);
        if (lane >= o) incl += v;
    }
    if (lane == 31) wsum[wid] = incl;
    __syncthreads();
    if (wid == 0) {
        int s = wsum[lane];
        #pragma unroll
        for (int o = 1; o < 32; o <<= 1) {
            int v = __shfl_up_sync(0xFFFFFFFFu, s, o);
            if (lane >= o) s += v;
        }
        wsum[lane] = s;
    }
    __syncthreads();
    int pos = (wid ? wsum[wid - 1] : 0) + incl - c;   // exclusive prefix
    #pragma unroll
    for (int q = 0; q < 3; q++) {
        unsigned ww = w[q];
        int wbase = (base + q) * 32;
        while (ww) {
            int b = __ffs(ww) - 1;
            ww &= ww - 1;
            int id = wbase + b;
            int lo = id / KJ, hi = id - lo * KJ;
            dout[pos * 4 + 0] = g_junc[2 * lo + 0];
            dout[pos * 4 + 1] = g_junc[2 * lo + 1];
            dout[pos * 4 + 2] = g_junc[2 * hi + 0];
            dout[pos * 4 + 3] = g_junc[2 * hi + 1];
            pos++;
        }
    }
    if (tid == 1023) g_count = wsum[31];
}

// ---------------- stage 5: LOI GEMM via tf32 MMA -> fp16 output ----------
__global__ void __launch_bounds__(256, 2)
k_loi_mma(const float* __restrict__ feat, const float* __restrict__ fc1w,
          const float* __restrict__ fc1b) {
    __shared__ float As[128][33];
    __shared__ float Bs[128][33];

    int tid  = threadIdx.x;
    int lane = tid & 31, wid = tid >> 5;
    int wm = (wid >> 2) * 64;
    int wn = (wid & 3) * 32;
    int g  = lane >> 2, tg = lane & 3;
    int p0 = blockIdx.x * 128;

    float c[4][4][4];
    #pragma unroll
    for (int mi = 0; mi < 4; mi++)
        #pragma unroll
        for (int ni = 0; ni < 4; ni++)
            #pragma unroll
            for (int r = 0; r < 4; r++) c[mi][ni][r] = 0.0f;

    for (int c0 = 0; c0 < 256; c0 += 32) {
        #pragma unroll
        for (int q = 0; q < 16; q++) {
            int f = tid + q * 256;
            int kc = f >> 7, p = f & 127;
            As[p][kc] = feat[(size_t)(c0 + kc) * HW + p0 + p];
        }
        #pragma unroll
        for (int q = 0; q < 16; q++) {
            int f = tid + q * 256;
            int cc = f & 31, o = f >> 5;
            Bs[o][cc] = fc1w[(size_t)o * 256 + c0 + cc];
        }
        __syncthreads();
        #pragma unroll
        for (int kk = 0; kk < 32; kk += 8) {
            unsigned a[4][4], b[4][2];
            #pragma unroll
            for (int mi = 0; mi < 4; mi++) {
                int r0 = wm + mi * 16 + g;
                a[mi][0] = __float_as_uint(As[r0][kk + tg]);
                a[mi][1] = __float_as_uint(As[r0 + 8][kk + tg]);
                a[mi][2] = __float_as_uint(As[r0][kk + tg + 4]);
                a[mi][3] = __float_as_uint(As[r0 + 8][kk + tg + 4]);
            }
            #pragma unroll
            for (int ni = 0; ni < 4; ni++) {
                int n0 = wn + ni * 8 + g;
                b[ni][0] = __float_as_uint(Bs[n0][kk + tg]);
                b[ni][1] = __float_as_uint(Bs[n0][kk + tg + 4]);
            }
            #pragma unroll
            for (int mi = 0; mi < 4; mi++)
                #pragma unroll
                for (int ni = 0; ni < 4; ni++)
                    asm volatile(
                        "mma.sync.aligned.m16n8k8.row.col.f32.tf32.tf32.f32 "
                        "{%0,%1,%2,%3}, {%4,%5,%6,%7}, {%8,%9}, {%0,%1,%2,%3};"
                        : "+f"(c[mi][ni][0]), "+f"(c[mi][ni][1]),
                          "+f"(c[mi][ni][2]), "+f"(c[mi][ni][3])
                        : "r"(a[mi][0]), "r"(a[mi][1]), "r"(a[mi][2]), "r"(a[mi][3]),
                          "r"(b[ni][0]), "r"(b[ni][1]));
        }
        __syncthreads();
    }

    #pragma unroll
    for (int mi = 0; mi < 4; mi++) {
        int p = p0 + wm + mi * 16 + g;
        #pragma unroll
        for (int ni = 0; ni < 4; ni++) {
            int o = wn + ni * 8 + 2 * tg;
            float bv0 = fc1b[o], bv1 = fc1b[o + 1];
            *(__half2*)&g_loi[(size_t)p * 128 + o] =
                __floats2half2_rn(c[mi][ni][0] + bv0, c[mi][ni][1] + bv1);
            *(__half2*)&g_loi[(size_t)(p + 8) * 128 + o] =
                __floats2half2_rn(c[mi][ni][2] + bv0, c[mi][ni][3] + bv1);
        }
    }
}

// ---------------- stage 6: bilinear sampling (half2, 2 lines/block) ----------------
__global__ void k_sample(const float* __restrict__ dout) {
    int M = g_count;
    int half = threadIdx.x >> 6;   // which of 2 lines
    int c2   = threadIdx.x & 63;   // half2 channel pair
    const __half2* loi2 = (const __half2*)g_loi;
    for (int m0 = blockIdx.x * 2; m0 < M; m0 += gridDim.x * 2) {
        int m = m0 + half;
        if (m >= M) break;
        float x1 = dout[m * 4 + 0], y1 = dout[m * 4 + 1];
        float x2 = dout[m * 4 + 2], y2 = dout[m * 4 + 3];
        float mx0 = 0.0f, mx1 = 0.0f;
        #pragma unroll 4
        for (int s = 0; s < 32; s++) {
            float t = (float)s / 31.0f;
            float px = x1 * t + x2 * (1.0f - t);
            float py = y1 * t + y2 * (1.0f - t);
            px = fminf(fmaxf(px, 0.0f), 127.0f);
            py = fminf(fmaxf(py, 0.0f), 127.0f);
            float fx0 = floorf(px), fy0 = floorf(py);
            int ix0 = (int)fx0, iy0 = (int)fy0;
            int ix1 = min(ix0 + 1, 127), iy1 = min(iy0 + 1, 127);
            float wx = px - fx0, wy = py - fy0;
            float2 v00 = __half22float2(loi2[(size_t)(iy0 * 128 + ix0) * 64 + c2]);
            float2 v01 = __half22float2(loi2[(size_t)(iy0 * 128 + ix1) * 64 + c2]);
            float2 v10 = __half22float2(loi2[(size_t)(iy1 * 128 + ix0) * 64 + c2]);
            float2 v11 = __half22float2(loi2[(size_t)(iy1 * 128 + ix1) * 64 + c2]);
            float w00 = (1.0f - wx) * (1.0f - wy), w01 = wx * (1.0f - wy);
            float w10 = (1.0f - wx) * wy,          w11 = wx * wy;
            float va = v00.x * w00 + v01.x * w01 + v10.x * w10 + v11.x * w11;
            float vb = v00.y * w00 + v01.y * w01 + v10.y * w10 + v11.y * w11;
            if ((s & 3) == 0) { mx0 = va; mx1 = vb; }
            else { mx0 = fmaxf(mx0, va); mx1 = fmaxf(mx1, vb); }
            if ((s & 3) == 3) {
                int j = s >> 2;
                g_bufA[(size_t)m * 1024 + (2 * c2) * 8 + j]     = __float2half(mx0);
                g_bufA[(size_t)m * 1024 + (2 * c2 + 1) * 8 + j] = __float2half(mx1);
            }
        }
    }
}

// ---------------- stage 7: persistent MLP GEMM, fp16 m16n8k16, optional fused final ---
__global__ void __launch_bounds__(256, 2)
k_mlp_mma(const __half* __restrict__ A, const __half* __restrict__ Wm,
          const float* __restrict__ bias, __half* __restrict__ Out,
          const float* __restrict__ w3) {
    __shared__ __align__(16) __half As[2][128][40];
    __shared__ __align__(16) __half Bs[2][128][40];

    int M = g_count;
    int tiles = ((M + 127) >> 7) * 8;
    int tid  = threadIdx.x;
    int lane = tid & 31, wid = tid >> 5;
    int wm = (wid >> 2) * 64;
    int wn = (wid & 3) * 32;
    int g  = lane >> 2, tg = lane & 3;

    for (int tile = blockIdx.x; tile < tiles; tile += gridDim.x) {
        int mt = tile >> 3, ot = tile & 7;
        const __half* Aptr = A  + (size_t)(mt * 128) * 1024;
        const __half* Bptr = Wm + (size_t)(ot * 128) * 1024;

        float c[4][4][4];
        #pragma unroll
        for (int mi = 0; mi < 4; mi++)
            #pragma unroll
            for (int ni = 0; ni < 4; ni++)
                #pragma unroll
                for (int r = 0; r < 4; r++) c[mi][ni][r] = 0.0f;

        #pragma unroll
        for (int st = 0; st < 2; st++) {
            int k0 = st * 32;
            #pragma unroll
            for (int q = 0; q < 2; q++) {
                int f = tid + q * 256;
                int row = f >> 2, ce = (f & 3) * 8;
                cp16(&As[st][row][ce], &Aptr[(size_t)row * 1024 + k0 + ce]);
                cp16(&Bs[st][row][ce], &Bptr[(size_t)row * 1024 + k0 + ce]);
            }
            cp_commit();
        }

        for (int kc = 0; kc < 32; kc++) {
            cp_wait1();
            __syncthreads();
            int st = kc & 1;
            #pragma unroll
            for (int kk = 0; kk < 32; kk += 16) {
                unsigned a[4][4], b[4][2];
                #pragma unroll
                for (int mi = 0; mi < 4; mi++) {
                    int r0 = wm + mi * 16 + g;
                    a[mi][0] = *(const unsigned*)&As[st][r0][kk + 2 * tg];
                    a[mi][1] = *(const unsigned*)&As[st][r0 + 8][kk + 2 * tg];
                    a[mi][2] = *(const unsigned*)&As[st][r0][kk + 2 * tg + 8];
                    a[mi][3] = *(const unsigned*)&As[st][r0 + 8][kk + 2 * tg + 8];
                }
                #pragma unroll
                for (int ni = 0; ni < 4; ni++) {
                    int n0 = wn + ni * 8 + g;
                    b[ni][0] = *(const unsigned*)&Bs[st][n0][kk + 2 * tg];
                    b[ni][1] = *(const unsigned*)&Bs[st][n0][kk + 2 * tg + 8];
                }
                #pragma unroll
                for (int mi = 0; mi < 4; mi++)
                    #pragma unroll
                    for (int ni = 0; ni < 4; ni++)
                        asm volatile(
                            "mma.sync.aligned.m16n8k16.row.col.f32.f16.f16.f32 "
                            "{%0,%1,%2,%3}, {%4,%5,%6,%7}, {%8,%9}, {%0,%1,%2,%3};"
                            : "+f"(c[mi][ni][0]), "+f"(c[mi][ni][1]),
                              "+f"(c[mi][ni][2]), "+f"(c[mi][ni][3])
                            : "r"(a[mi][0]), "r"(a[mi][1]), "r"(a[mi][2]), "r"(a[mi][3]),
                              "r"(b[ni][0]), "r"(b[ni][1]));
            }
            __syncthreads();
            if (kc < 30) {
                int k0 = (kc + 2) * 32;
                #pragma unroll
                for (int q = 0; q < 2; q++) {
                    int f = tid + q * 256;
                    int row = f >> 2, ce = (f & 3) * 8;
                    cp16(&As[st][row][ce], &Aptr[(size_t)row * 1024 + k0 + ce]);
                    cp16(&Bs[st][row][ce], &Bptr[(size_t)row * 1024 + k0 + ce]);
                }
                cp_commit();
            }
        }

        if (w3 == nullptr) {
            // epilogue: bias + relu -> fp16 store
            #pragma unroll
            for (int mi = 0; mi < 4; mi++) {
                int m0 = mt * 128 + wm + mi * 16 + g;
                #pragma unroll
                for (int ni = 0; ni < 4; ni++) {
                    int o = ot * 128 + wn + ni * 8 + 2 * tg;
                    float bv0 = bias[o], bv1 = bias[o + 1];
                    if (m0 < M) {
                        *(__half2*)&Out[(size_t)m0 * 1024 + o] =
                            __floats2half2_rn(fmaxf(c[mi][ni][0] + bv0, 0.0f),
                                              fmaxf(c[mi][ni][1] + bv1, 0.0f));
                    }
                    if (m0 + 8 < M) {
                        *(__half2*)&Out[(size_t)(m0 + 8) * 1024 + o] =
                            __floats2half2_rn(fmaxf(c[mi][ni][2] + bv0, 0.0f),
                                              fmaxf(c[mi][ni][3] + bv1, 0.0f));
                    }
                }
            }
        } else {
            // fused final: partial dot of relu(h2) with w3, no h2 store
            float pm0[4], pm1[4];
            #pragma unroll
            for (int mi = 0; mi < 4; mi++) { pm0[mi] = 0.0f; pm1[mi] = 0.0f; }
            #pragma unroll
            for (int mi = 0; mi < 4; mi++)
                #pragma unroll
                for (int ni = 0; ni < 4; ni++) {
                    int o = ot * 128 + wn + ni * 8 + 2 * tg;
                    float bv0 = bias[o], bv1 = bias[o + 1];
                    float w0 = w3[o], w1 = w3[o + 1];
                    pm0[mi] += fmaxf(c[mi][ni][0] + bv0, 0.0f) * w0
                             + fmaxf(c[mi][ni][1] + bv1, 0.0f) * w1;
                    pm1[mi] += fmaxf(c[mi][ni][2] + bv0, 0.0f) * w0
                             + fmaxf(c[mi][ni][3] + bv1, 0.0f) * w1;
                }
            #pragma unroll
            for (int mi = 0; mi < 4; mi++) {
                pm0[mi] += __shfl_xor_sync(0xFFFFFFFFu, pm0[mi], 1);
                pm0[mi] += __shfl_xor_sync(0xFFFFFFFFu, pm0[mi], 2);
                pm1[mi] += __shfl_xor_sync(0xFFFFFFFFu, pm1[mi], 1);
                pm1[mi] += __shfl_xor_sync(0xFFFFFFFFu, pm1[mi], 2);
            }
            if (tg == 0) {
                int slot = ot * 4 + (wid & 3);
                #pragma unroll
                for (int mi = 0; mi < 4; mi++) {
                    int m0 = mt * 128 + wm + mi * 16 + g;
                    if (m0 < M)     g_part[(size_t)m0 * 32 + slot]       = pm0[mi];
                    if (m0 + 8 < M) g_part[(size_t)(m0 + 8) * 32 + slot] = pm1[mi];
                }
            }
        }
    }
}

// ---------------- stage 8: deterministic partial-sum + sigmoid ----------------
__global__ void k_sig(const float* __restrict__ b3, float* __restrict__ dout) {
    int M = g_count;
    int m = blockIdx.x * blockDim.x + threadIdx.x;
    if (m >= M) return;
    float acc = b3[0];
    #pragma unroll
    for (int i = 0; i < 32; i++) acc += g_part[(size_t)m * 32 + i];
    dout[4 * NLINES + m] = 1.0f / (1.0f + expf(-acc));
}

// ---------------- launch ----------------
extern "C" void kernel_launch(void* const* d_in, const int* in_sizes, int n_in,
                              void* d_out, int out_size) {
    const float* features = (const float*)d_in[0];
    const float* heatmaps = (const float*)d_in[1];
    const float* fc1_w    = (const float*)d_in[2];
    const float* fc1_b    = (const float*)d_in[3];
    const float* w1       = (const float*)d_in[4];
    const float* b1       = (const float*)d_in[5];
    const float* w2       = (const float*)d_in[6];
    const float* b2       = (const float*)d_in[7];
    const float* w3       = (const float*)d_in[8];
    const float* b3       = (const float*)d_in[9];
    float* dout = (float*)d_out;

    static cudaStream_t s2 = nullptr;
    static cudaEvent_t evFork = nullptr, evJoin = nullptr;
    if (!s2) {
        cudaStreamCreateWithFlags(&s2, cudaStreamNonBlocking);
        cudaEventCreateWithFlags(&evFork, cudaEventDisableTiming);
        cudaEventCreateWithFlags(&evJoin, cudaEventDisableTiming);
        cudaFuncSetAttribute(k_front, cudaFuncAttributeMaxDynamicSharedMemorySize, 98304);
    }

    void *p_count, *p_bitmap;
    cudaGetSymbolAddress(&p_count,  g_count);
    cudaGetSymbolAddress(&p_bitmap, g_bitmap);
    (void)in_sizes; (void)n_in;

    cudaMemsetAsync(p_count,  0, sizeof(int));
    cudaMemsetAsync(p_bitmap, 0, sizeof(unsigned int) * NBMW);
    cudaMemsetAsync(dout,     0, (size_t)out_size * sizeof(float));

    // fork: weight cvt + LOI GEMM on side stream, overlapping the front-end chain
    cudaEventRecord(evFork, 0);
    cudaStreamWaitEvent(s2, evFork, 0);
    k_cvt<<<4096, 256, 0, s2>>>(w1, w2);
    k_loi_mma<<<128, 256, 0, s2>>>(features, fc1_w, fc1_b);
    cudaEventRecord(evJoin, s2);

    k_front<<<1, 1024, 98304>>>(heatmaps);
    k_match<<<384, 256>>>(heatmaps);
    k_compact<<<1, 1024>>>(dout);

    cudaStreamWaitEvent(0, evJoin, 0);
    k_sample<<<512, 128>>>(dout);

    __half* A = nullptr; __half* B = nullptr; __half* W1 = nullptr; __half* W2 = nullptr;
    cudaGetSymbolAddress((void**)&A,  g_bufA);
    cudaGetSymbolAddress((void**)&B,  g_bufB);
    cudaGetSymbolAddress((void**)&W1, g_w1h);
    cudaGetSymbolAddress((void**)&W2, g_w2h);

    k_mlp_mma<<<296, 256>>>(A, W1, b1, B, nullptr);
    k_mlp_mma<<<296, 256>>>(B, W2, b2, A, w3);
    k_sig<<<176, 256>>>(b3, dout);
}

// round 13
// speedup vs baseline: 1.2412x; 1.2412x over previous
#include <cuda_runtime.h>
#include <cuda_fp16.h>
#include <math.h>

#define HW      16384
#define KJ      300
#define NLINES  49152
#define NBMW    2816            // 2816*32 = 90112 >= 90000 bits
#define MPAD    44928           // ceil(44850/128)*128
#define PI_F    3.14159265358979323846f

// ---------------- scratch (static device memory; no allocations) ----------------
__device__ unsigned long long  g_cand[4096];
__device__ int                 g_ctrs[2];     // [0]=cand count, [1]=line count
__device__ float               g_junc[2 * KJ];
__device__ unsigned int        g_bitmap[NBMW];
__device__ __align__(128) __half g_loi[(size_t)HW * 128];      // [pixel][channel] fp16
__device__ __align__(128) __half g_bufA[(size_t)MPAD * 1024];  // feats (fp16)
__device__ __align__(128) __half g_bufB[(size_t)MPAD * 1024];  // h1 (fp16)
__device__ __align__(128) __half g_w1h[1024 * 1024];
__device__ __align__(128) __half g_w2h[1024 * 1024];

__device__ __forceinline__ float sigm(float x) { return 1.0f / (1.0f + expf(-x)); }

__device__ __forceinline__ void cp16(void* smem, const void* gptr) {
    unsigned s = (unsigned)__cvta_generic_to_shared(smem);
    asm volatile("cp.async.cg.shared.global [%0], [%1], 16;" :: "r"(s), "l"(gptr));
}
__device__ __forceinline__ void cp_commit() { asm volatile("cp.async.commit_group;"); }
__device__ __forceinline__ void cp_wait1()  { asm volatile("cp.async.wait_group 1;"); }

// ---------------- stage 0 (side stream): fp16 weight conversion ----------------
__global__ void k_cvt(const float* __restrict__ w1, const float* __restrict__ w2) {
    int i = blockIdx.x * blockDim.x + threadIdx.x;   // 0 .. 1M-1
    g_w1h[i] = __float2half(w1[i]);
    g_w2h[i] = __float2half(w2[i]);
}

// ---------------- stage 1 (fused): jloc + 3x3 NMS + candidate gather ----------------
__device__ __forceinline__ float jl(const float* __restrict__ heat, int p) {
    return 1.0f / (1.0f + expf(heat[5 * HW + p] - heat[6 * HW + p]));
}
__global__ void k_prop(const float* __restrict__ heat) {
    int i = blockIdx.x * blockDim.x + threadIdx.x;
    if (i >= HW) return;
    int y = i >> 7, x = i & 127;
    float v = jl(heat, i);
    float m = v;
    for (int dy = -1; dy <= 1; dy++) {
        int yy = y + dy; if ((unsigned)yy >= 128u) continue;
        for (int dx = -1; dx <= 1; dx++) {
            if (dy == 0 && dx == 0) continue;
            int xx = x + dx; if ((unsigned)xx >= 128u) continue;
            m = fmaxf(m, jl(heat, yy * 128 + xx));
        }
    }
    if (v == m && v > 0.0f) {
        int p = atomicAdd(&g_ctrs[0], 1);
        if (p < 4096) {
            unsigned long long key =
                ((unsigned long long)__float_as_uint(v) << 32) |
                (unsigned long long)(0xFFFFFFFFu - (unsigned)i);   // ties: lower idx first
            g_cand[p] = key;
        }
    }
}

// ---------------- stage 2: histogram select + small bitonic sort + junction coords ----
__global__ void k_topk_sel(const float* __restrict__ heat) {
    __shared__ unsigned long long sbuf[4096];   // aliased as 8192-bin u32 histogram
    __shared__ int sc[1024];
    __shared__ int sB, sTot, sPos;
    unsigned int* hist = (unsigned int*)sbuf;
    int t = threadIdx.x;
    int cc = g_ctrs[0];
    if (cc > 4096) cc = 4096;

    #pragma unroll
    for (int q = 0; q < 8; q++) hist[q * 1024 + t] = 0u;
    if (t == 0) { sPos = 0; sB = 0; sTot = 0; }
    __syncthreads();

    unsigned long long kk[4];
    #pragma unroll
    for (int q = 0; q < 4; q++) {
        int idx = q * 1024 + t;
        unsigned long long key = (idx < cc) ? g_cand[idx] : 0ULL;
        kk[q] = key;
        if (key >> 32)
            atomicAdd(&hist[(int)((key >> 50) & 0x1FFF)], 1u);
    }
    __syncthreads();

    int gs = 0;
    #pragma unroll
    for (int b = 0; b < 8; b++) gs += hist[t * 8 + b];
    sc[t] = gs;
    __syncthreads();
    for (int off = 1; off < 1024; off <<= 1) {
        int v = (t + off < 1024) ? sc[t + off] : 0;
        __syncthreads();
        sc[t] += v;
        __syncthreads();
    }
    int sufN = (t < 1023) ? sc[t + 1] : 0;
    if (t == 0 && sc[0] < KJ) { sB = 0; sTot = sc[0]; }
    if (sc[0] >= KJ && sc[t] >= KJ && sufN < KJ) {
        int run = sufN;
        for (int b = t * 8 + 7; b >= t * 8; b--) {
            run += hist[b];
            if (run >= KJ) { sB = b; sTot = run; break; }
        }
    }
    __syncthreads();
    int B = sB, total = sTot;

    #pragma unroll
    for (int q = 0; q < 4; q++) {
        unsigned long long key = kk[q];
        if ((key >> 32) && (int)((key >> 50) & 0x1FFF) >= B) {
            int p = atomicAdd(&sPos, 1);
            sbuf[p] = key;
        }
    }
    __syncthreads();

    int n = (total <= 512) ? 512 : (total <= 1024) ? 1024 : (total <= 2048) ? 2048 : 4096;
    for (int i = total + t; i < n; i += 1024) sbuf[i] = 0ULL;
    __syncthreads();

    for (int k = 2; k <= n; k <<= 1) {
        for (int j = k >> 1; j > 0; j >>= 1) {
            for (int i = t; i < n; i += 1024) {
                int ixj = i ^ j;
                if (ixj > i) {
                    unsigned long long a = sbuf[i], b = sbuf[ixj];
                    bool descSeg = (i & k) == 0;
                    if (descSeg ? (a < b) : (a > b)) { sbuf[i] = b; sbuf[ixj] = a; }
                }
            }
            __syncthreads();
        }
    }

    if (t < KJ) {
        unsigned long long key = sbuf[t];
        float v = __uint_as_float((unsigned)(key >> 32));
        if (v > 0.008f) {
            unsigned pix = 0xFFFFFFFFu - (unsigned)(key & 0xFFFFFFFFu);
            float x = (float)(pix & 127u), y = (float)(pix >> 7);
            g_junc[2 * t + 0] = x + sigm(heat[7 * HW + pix]);
            g_junc[2 * t + 1] = y + sigm(heat[8 * HW + pix]);
        } else {
            g_junc[2 * t + 0] = 1e6f;
            g_junc[2 * t + 1] = 1e6f;
        }
    }
}

// ---------------- stage 3: HAFM decode + junction matching + id bitmap ----------------
// (round-7 form: one thread handles both endpoints of a line; 17.7us measured vs
//  26.5us for the 1-endpoint/thread split)
__global__ void k_match(const float* __restrict__ heat) {
    __shared__ float sj[2 * KJ];
    for (int i = threadIdx.x; i < 2 * KJ; i += blockDim.x) sj[i] = g_junc[i];
    __syncthreads();
    int n = blockIdx.x * blockDim.x + threadIdx.x;
    if (n >= NLINES) return;
    int ch = n >> 14;
    int pix = n & (HW - 1);
    float x0 = (float)(pix & 127), y0 = (float)(pix >> 7);
    float a0   = sigm(heat[0 * HW + pix]);
    float a1   = sigm(heat[1 * HW + pix]);
    float a2   = sigm(heat[2 * HW + pix]);
    float dist = sigm(heat[3 * HW + pix]);
    float bias = sigm(heat[4 * HW + pix]);
    float d = dist + bias * (float)(ch - 1);
    d = fminf(fmaxf(d, 0.0f), 1.0f);
    float ang0 = (a0 - 0.5f) * PI_F * 2.0f;
    float c0 = cosf(ang0), s0 = sinf(ang0);
    float t1 =  tanf(a1 * (PI_F * 0.5f));
    float t2 = -tanf(a2 * (PI_F * 0.5f));
    float e1x = fminf(fmaxf((c0 - s0 * t1) * d * 5.0f + x0, 0.0f), 127.0f);
    float e1y = fminf(fmaxf((s0 + c0 * t1) * d * 5.0f + y0, 0.0f), 127.0f);
    float e2x = fminf(fmaxf((c0 - s0 * t2) * d * 5.0f + x0, 0.0f), 127.0f);
    float e2y = fminf(fmaxf((s0 + c0 * t2) * d * 5.0f + y0, 0.0f), 127.0f);

    int j1 = 0, j2 = 0;
    float m1 = 3.4e38f, m2 = 3.4e38f;
    const float2* sj2 = (const float2*)sj;
    #pragma unroll 4
    for (int k = 0; k < KJ; k++) {
        float2 jxy = sj2[k];
        float dx = jxy.x - e1x, dy = jxy.y - e1y;
        float dd = dx * dx + dy * dy;
        if (dd < m1) { m1 = dd; j1 = k; }
        dx = jxy.x - e2x; dy = jxy.y - e2y;
        dd = dx * dx + dy * dy;
        if (dd < m2) { m2 = dd; j2 = k; }
    }
    int lo = min(j1, j2), hi = max(j1, j2);
    if (lo < hi) {
        int id = lo * KJ + hi;
        atomicOr(&g_bitmap[id >> 5], 1u << (id & 31));
    }
}

// ---------------- stage 4: ordered bitmap compaction (warp-scan) ----------------
__global__ void k_compact(float* __restrict__ dout) {
    __shared__ int wsum[32];
    int tid = threadIdx.x;
    int lane = tid & 31, wid = tid >> 5;
    int base = tid * 3;
    unsigned w[3] = {0u, 0u, 0u};
    int c = 0;
    #pragma unroll
    for (int q = 0; q < 3; q++) {
        int wi = base + q;
        if (wi < NBMW) { w[q] = g_bitmap[wi]; c += __popc(w[q]); }
    }
    int incl = c;
    #pragma unroll
    for (int o = 1; o < 32; o <<= 1) {
        int v = __shfl_up_sync(0xFFFFFFFFu, incl, o);
        if (lane >= o) incl += v;
    }
    if (lane == 31) wsum[wid] = incl;
    __syncthreads();
    if (wid == 0) {
        int s = wsum[lane];
        #pragma unroll
        for (int o = 1; o < 32; o <<= 1) {
            int v = __shfl_up_sync(0xFFFFFFFFu, s, o);
            if (lane >= o) s += v;
        }
        wsum[lane] = s;
    }
    __syncthreads();
    int pos = (wid ? wsum[wid - 1] : 0) + incl - c;   // exclusive prefix
    #pragma unroll
    for (int q = 0; q < 3; q++) {
        unsigned ww = w[q];
        int wbase = (base + q) * 32;
        while (ww) {
            int b = __ffs(ww) - 1;
            ww &= ww - 1;
            int id = wbase + b;
            int lo = id / KJ, hi = id - lo * KJ;
            dout[pos * 4 + 0] = g_junc[2 * lo + 0];
            dout[pos * 4 + 1] = g_junc[2 * lo + 1];
            dout[pos * 4 + 2] = g_junc[2 * hi + 0];
            dout[pos * 4 + 3] = g_junc[2 * hi + 1];
            pos++;
        }
    }
    if (tid == 1023) g_ctrs[1] = wsum[31];
}

// ---------------- stage 5: LOI GEMM via tf32 MMA -> fp16 output ----------
__global__ void __launch_bounds__(256, 2)
k_loi_mma(const float* __restrict__ feat, const float* __restrict__ fc1w,
          const float* __restrict__ fc1b) {
    __shared__ float As[128][33];
    __shared__ float Bs[128][33];

    int tid  = threadIdx.x;
    int lane = tid & 31, wid = tid >> 5;
    int wm = (wid >> 2) * 64;
    int wn = (wid & 3) * 32;
    int g  = lane >> 2, tg = lane & 3;
    int p0 = blockIdx.x * 128;

    float c[4][4][4];
    #pragma unroll
    for (int mi = 0; mi < 4; mi++)
        #pragma unroll
        for (int ni = 0; ni < 4; ni++)
            #pragma unroll
            for (int r = 0; r < 4; r++) c[mi][ni][r] = 0.0f;

    for (int c0 = 0; c0 < 256; c0 += 32) {
        #pragma unroll
        for (int q = 0; q < 16; q++) {
            int f = tid + q * 256;
            int kc = f >> 7, p = f & 127;
            As[p][kc] = feat[(size_t)(c0 + kc) * HW + p0 + p];
        }
        #pragma unroll
        for (int q = 0; q < 16; q++) {
            int f = tid + q * 256;
            int cc = f & 31, o = f >> 5;
            Bs[o][cc] = fc1w[(size_t)o * 256 + c0 + cc];
        }
        __syncthreads();
        #pragma unroll
        for (int kk = 0; kk < 32; kk += 8) {
            unsigned a[4][4], b[4][2];
            #pragma unroll
            for (int mi = 0; mi < 4; mi++) {
                int r0 = wm + mi * 16 + g;
                a[mi][0] = __float_as_uint(As[r0][kk + tg]);
                a[mi][1] = __float_as_uint(As[r0 + 8][kk + tg]);
                a[mi][2] = __float_as_uint(As[r0][kk + tg + 4]);
                a[mi][3] = __float_as_uint(As[r0 + 8][kk + tg + 4]);
            }
            #pragma unroll
            for (int ni = 0; ni < 4; ni++) {
                int n0 = wn + ni * 8 + g;
                b[ni][0] = __float_as_uint(Bs[n0][kk + tg]);
                b[ni][1] = __float_as_uint(Bs[n0][kk + tg + 4]);
            }
            #pragma unroll
            for (int mi = 0; mi < 4; mi++)
                #pragma unroll
                for (int ni = 0; ni < 4; ni++)
                    asm volatile(
                        "mma.sync.aligned.m16n8k8.row.col.f32.tf32.tf32.f32 "
                        "{%0,%1,%2,%3}, {%4,%5,%6,%7}, {%8,%9}, {%0,%1,%2,%3};"
                        : "+f"(c[mi][ni][0]), "+f"(c[mi][ni][1]),
                          "+f"(c[mi][ni][2]), "+f"(c[mi][ni][3])
                        : "r"(a[mi][0]), "r"(a[mi][1]), "r"(a[mi][2]), "r"(a[mi][3]),
                          "r"(b[ni][0]), "r"(b[ni][1]));
        }
        __syncthreads();
    }

    #pragma unroll
    for (int mi = 0; mi < 4; mi++) {
        int p = p0 + wm + mi * 16 + g;
        #pragma unroll
        for (int ni = 0; ni < 4; ni++) {
            int o = wn + ni * 8 + 2 * tg;
            float bv0 = fc1b[o], bv1 = fc1b[o + 1];
            *(__half2*)&g_loi[(size_t)p * 128 + o] =
                __floats2half2_rn(c[mi][ni][0] + bv0, c[mi][ni][1] + bv1);
            *(__half2*)&g_loi[(size_t)(p + 8) * 128 + o] =
                __floats2half2_rn(c[mi][ni][2] + bv0, c[mi][ni][3] + bv1);
        }
    }
}

// ---------------- stage 6: bilinear sampling + maxpool4 -> feats[m][1024] fp16 --------
__global__ void k_sample(const float* __restrict__ dout) {
    int M = g_ctrs[1];
    int ch = threadIdx.x;      // 128 threads, one channel each
    for (int m = blockIdx.x; m < M; m += gridDim.x) {
        float x1 = dout[m * 4 + 0], y1 = dout[m * 4 + 1];
        float x2 = dout[m * 4 + 2], y2 = dout[m * 4 + 3];
        float mx = -3.4e38f;
        #pragma unroll 4
        for (int s = 0; s < 32; s++) {
            float t = (float)s / 31.0f;
            float px = x1 * t + x2 * (1.0f - t);
            float py = y1 * t + y2 * (1.0f - t);
            px = fminf(fmaxf(px, 0.0f), 127.0f);
            py = fminf(fmaxf(py, 0.0f), 127.0f);
            float fx0 = floorf(px), fy0 = floorf(py);
            int ix0 = (int)fx0, iy0 = (int)fy0;
            int ix1 = min(ix0 + 1, 127), iy1 = min(iy0 + 1, 127);
            float wx = px - fx0, wy = py - fy0;
            float v00 = __half2float(g_loi[(size_t)(iy0 * 128 + ix0) * 128 + ch]);
            float v01 = __half2float(g_loi[(size_t)(iy0 * 128 + ix1) * 128 + ch]);
            float v10 = __half2float(g_loi[(size_t)(iy1 * 128 + ix0) * 128 + ch]);
            float v11 = __half2float(g_loi[(size_t)(iy1 * 128 + ix1) * 128 + ch]);
            float v = v00 * (1.0f - wx) * (1.0f - wy) + v01 * wx * (1.0f - wy)
                    + v10 * (1.0f - wx) * wy + v11 * wx * wy;
            mx = ((s & 3) == 0) ? v : fmaxf(mx, v);
            if ((s & 3) == 3) g_bufA[(size_t)m * 1024 + ch * 8 + (s >> 2)] = __float2half(mx);
        }
    }
}

// ---------------- stage 7: persistent MLP GEMM, fp16 m16n8k16, 2-stage cp.async ------
__global__ void __launch_bounds__(256, 2)
k_mlp_mma(const __half* __restrict__ A, const __half* __restrict__ Wm,
          const float* __restrict__ bias, __half* __restrict__ Out) {
    __shared__ __align__(16) __half As[2][128][40];   // 80B row stride: conflict-free
    __shared__ __align__(16) __half Bs[2][128][40];

    int M = g_ctrs[1];
    int tiles = ((M + 127) >> 7) * 8;
    int tid  = threadIdx.x;
    int lane = tid & 31, wid = tid >> 5;
    int wm = (wid >> 2) * 64;
    int wn = (wid & 3) * 32;
    int g  = lane >> 2, tg = lane & 3;

    for (int tile = blockIdx.x; tile < tiles; tile += gridDim.x) {
        int mt = tile >> 3, ot = tile & 7;
        const __half* Aptr = A  + (size_t)(mt * 128) * 1024;
        const __half* Bptr = Wm + (size_t)(ot * 128) * 1024;

        float c[4][4][4];
        #pragma unroll
        for (int mi = 0; mi < 4; mi++)
            #pragma unroll
            for (int ni = 0; ni < 4; ni++)
                #pragma unroll
                for (int r = 0; r < 4; r++) c[mi][ni][r] = 0.0f;

        // prologue: stages 0 (k0=0) and 1 (k0=32)
        #pragma unroll
        for (int st = 0; st < 2; st++) {
            int k0 = st * 32;
            #pragma unroll
            for (int q = 0; q < 2; q++) {
                int f = tid + q * 256;
                int row = f >> 2, ce = (f & 3) * 8;
                cp16(&As[st][row][ce], &Aptr[(size_t)row * 1024 + k0 + ce]);
                cp16(&Bs[st][row][ce], &Bptr[(size_t)row * 1024 + k0 + ce]);
            }
            cp_commit();
        }

        for (int kc = 0; kc < 32; kc++) {
            cp_wait1();
            __syncthreads();
            int st = kc & 1;
            #pragma unroll
            for (int kk = 0; kk < 32; kk += 16) {
                unsigned a[4][4], b[4][2];
                #pragma unroll
                for (int mi = 0; mi < 4; mi++) {
                    int r0 = wm + mi * 16 + g;
                    a[mi][0] = *(const unsigned*)&As[st][r0][kk + 2 * tg];
                    a[mi][1] = *(const unsigned*)&As[st][r0 + 8][kk + 2 * tg];
                    a[mi][2] = *(const unsigned*)&As[st][r0][kk + 2 * tg + 8];
                    a[mi][3] = *(const unsigned*)&As[st][r0 + 8][kk + 2 * tg + 8];
                }
                #pragma unroll
                for (int ni = 0; ni < 4; ni++) {
                    int n0 = wn + ni * 8 + g;
                    b[ni][0] = *(const unsigned*)&Bs[st][n0][kk + 2 * tg];
                    b[ni][1] = *(const unsigned*)&Bs[st][n0][kk + 2 * tg + 8];
                }
                #pragma unroll
                for (int mi = 0; mi < 4; mi++)
                    #pragma unroll
                    for (int ni = 0; ni < 4; ni++)
                        asm volatile(
                            "mma.sync.aligned.m16n8k16.row.col.f32.f16.f16.f32 "
                            "{%0,%1,%2,%3}, {%4,%5,%6,%7}, {%8,%9}, {%0,%1,%2,%3};"
                            : "+f"(c[mi][ni][0]), "+f"(c[mi][ni][1]),
                              "+f"(c[mi][ni][2]), "+f"(c[mi][ni][3])
                            : "r"(a[mi][0]), "r"(a[mi][1]), "r"(a[mi][2]), "r"(a[mi][3]),
                              "r"(b[ni][0]), "r"(b[ni][1]));
            }
            __syncthreads();
            if (kc < 30) {
                int k0 = (kc + 2) * 32;
                #pragma unroll
                for (int q = 0; q < 2; q++) {
                    int f = tid + q * 256;
                    int row = f >> 2, ce = (f & 3) * 8;
                    cp16(&As[st][row][ce], &Aptr[(size_t)row * 1024 + k0 + ce]);
                    cp16(&Bs[st][row][ce], &Bptr[(size_t)row * 1024 + k0 + ce]);
                }
                cp_commit();
            }
        }

        // epilogue: bias + relu -> fp16
        #pragma unroll
        for (int mi = 0; mi < 4; mi++) {
            int m0 = mt * 128 + wm + mi * 16 + g;
            #pragma unroll
            for (int ni = 0; ni < 4; ni++) {
                int o = ot * 128 + wn + ni * 8 + 2 * tg;
                float bv0 = bias[o], bv1 = bias[o + 1];
                if (m0 < M) {
                    *(__half2*)&Out[(size_t)m0 * 1024 + o] =
                        __floats2half2_rn(fmaxf(c[mi][ni][0] + bv0, 0.0f),
                                          fmaxf(c[mi][ni][1] + bv1, 0.0f));
                }
                if (m0 + 8 < M) {
                    *(__half2*)&Out[(size_t)(m0 + 8) * 1024 + o] =
                        __floats2half2_rn(fmaxf(c[mi][ni][2] + bv0, 0.0f),
                                          fmaxf(c[mi][ni][3] + bv1, 0.0f));
                }
            }
        }
    }
}

// ---------------- stage 8: final dot + sigmoid ----------------
__global__ void k_final(const __half* __restrict__ h2, const float* __restrict__ w3,
                        const float* __restrict__ b3, float* __restrict__ dout) {
    int M = g_ctrs[1];
    int gtid = blockIdx.x * blockDim.x + threadIdx.x;
    int warp = gtid >> 5;
    int lane = threadIdx.x & 31;
    int nwarps = (gridDim.x * blockDim.x) >> 5;
    for (int m = warp; m < M; m += nwarps) {
        float acc = 0.0f;
        #pragma unroll 8
        for (int c = lane; c < 1024; c += 32)
            acc += __half2float(h2[(size_t)m * 1024 + c]) * w3[c];
        #pragma unroll
        for (int o = 16; o > 0; o >>= 1) acc += __shfl_xor_sync(0xFFFFFFFFu, acc, o);
        if (lane == 0)
            dout[4 * NLINES + m] = 1.0f / (1.0f + expf(-(acc + b3[0])));
    }
}

// ---------------- launch ----------------
extern "C" void kernel_launch(void* const* d_in, const int* in_sizes, int n_in,
                              void* d_out, int out_size) {
    const float* features = (const float*)d_in[0];
    const float* heatmaps = (const float*)d_in[1];
    const float* fc1_w    = (const float*)d_in[2];
    const float* fc1_b    = (const float*)d_in[3];
    const float* w1       = (const float*)d_in[4];
    const float* b1       = (const float*)d_in[5];
    const float* w2       = (const float*)d_in[6];
    const float* b2       = (const float*)d_in[7];
    const float* w3       = (const float*)d_in[8];
    const float* b3       = (const float*)d_in[9];
    float* dout = (float*)d_out;

    static cudaStream_t s2 = nullptr;
    static cudaEvent_t evFork = nullptr, evJoin = nullptr;
    if (!s2) {
        cudaStreamCreateWithFlags(&s2, cudaStreamNonBlocking);
        cudaEventCreateWithFlags(&evFork, cudaEventDisableTiming);
        cudaEventCreateWithFlags(&evJoin, cudaEventDisableTiming);
    }

    void *p_ctrs, *p_bitmap;
    cudaGetSymbolAddress(&p_ctrs,   g_ctrs);
    cudaGetSymbolAddress(&p_bitmap, g_bitmap);
    (void)in_sizes; (void)n_in;

    cudaMemsetAsync(p_ctrs,   0, sizeof(int) * 2);
    cudaMemsetAsync(p_bitmap, 0, sizeof(unsigned int) * NBMW);
    cudaMemsetAsync(dout,     0, (size_t)out_size * sizeof(float));

    // fork: weight cvt + LOI GEMM on side stream, overlapping the front-end chain
    cudaEventRecord(evFork, 0);
    cudaStreamWaitEvent(s2, evFork, 0);
    k_cvt<<<4096, 256, 0, s2>>>(w1, w2);
    k_loi_mma<<<128, 256, 0, s2>>>(features, fc1_w, fc1_b);
    cudaEventRecord(evJoin, s2);

    k_prop<<<64, 256>>>(heatmaps);
    k_topk_sel<<<1, 1024>>>(heatmaps);
    k_match<<<192, 256>>>(heatmaps);
    k_compact<<<1, 1024>>>(dout);

    cudaStreamWaitEvent(0, evJoin, 0);
    k_sample<<<512, 128>>>(dout);

    __half* A = nullptr; __half* B = nullptr; __half* W1 = nullptr; __half* W2 = nullptr;
    cudaGetSymbolAddress((void**)&A,  g_bufA);
    cudaGetSymbolAddress((void**)&B,  g_bufB);
    cudaGetSymbolAddress((void**)&W1, g_w1h);
    cudaGetSymbolAddress((void**)&W2, g_w2h);

    k_mlp_mma<<<296, 256>>>(A, W1, b1, B);
    k_mlp_mma<<<296, 256>>>(B, W2, b2, A);
    k_final<<<256, 128>>>(A, w3, b3, dout);
}

// round 16
// speedup vs baseline: 1.4146x; 1.1398x over previous
#include <cuda_runtime.h>
#include <cuda_fp16.h>
#include <math.h>

#define HW      16384
#define KJ      300
#define NLINES  49152
#define NBMW    2816            // 2816*32 = 90112 >= 90000 bits
#define MPAD    44928           // ceil(44850/128)*128
#define PI_F    3.14159265358979323846f

// ---------------- scratch (static device memory; no allocations) ----------------
__device__ unsigned long long  g_cand[4096];
__device__ int                 g_ctrs[2];     // [0]=cand count, [1]=line count
__device__ float               g_junc[2 * KJ];
__device__ unsigned int        g_bitmap[NBMW];
__device__ __align__(128) __half g_loi[(size_t)HW * 128];      // [pixel][channel] fp16
__device__ __align__(128) __half g_bufA[(size_t)MPAD * 1024];  // feats (fp16)
__device__ __align__(128) __half g_bufB[(size_t)MPAD * 1024];  // h1 (fp16)
__device__ __align__(128) __half g_w1h[1024 * 1024];
__device__ __align__(128) __half g_w2h[1024 * 1024];

__device__ __forceinline__ float sigm(float x) { return 1.0f / (1.0f + expf(-x)); }

__device__ __forceinline__ void cp16(void* smem, const void* gptr) {
    unsigned s = (unsigned)__cvta_generic_to_shared(smem);
    asm volatile("cp.async.cg.shared.global [%0], [%1], 16;" :: "r"(s), "l"(gptr));
}
__device__ __forceinline__ void cp_commit() { asm volatile("cp.async.commit_group;"); }
__device__ __forceinline__ void cp_wait1()  { asm volatile("cp.async.wait_group 1;"); }

// ---------------- stage 0 (side stream): fp16 weight conversion ----------------
__global__ void k_cvt(const float* __restrict__ w1, const float* __restrict__ w2) {
    int i = blockIdx.x * blockDim.x + threadIdx.x;   // 0 .. 1M-1
    g_w1h[i] = __float2half(w1[i]);
    g_w2h[i] = __float2half(w2[i]);
}

// ---------------- stage 1 (fused): jloc + 3x3 NMS + candidate gather ----------------
__device__ __forceinline__ float jl(const float* __restrict__ heat, int p) {
    return 1.0f / (1.0f + expf(heat[5 * HW + p] - heat[6 * HW + p]));
}
__global__ void k_prop(const float* __restrict__ heat) {
    int i = blockIdx.x * blockDim.x + threadIdx.x;
    if (i >= HW) return;
    int y = i >> 7, x = i & 127;
    float v = jl(heat, i);
    float m = v;
    for (int dy = -1; dy <= 1; dy++) {
        int yy = y + dy; if ((unsigned)yy >= 128u) continue;
        for (int dx = -1; dx <= 1; dx++) {
            if (dy == 0 && dx == 0) continue;
            int xx = x + dx; if ((unsigned)xx >= 128u) continue;
            m = fmaxf(m, jl(heat, yy * 128 + xx));
        }
    }
    if (v == m && v > 0.0f) {
        int p = atomicAdd(&g_ctrs[0], 1);
        if (p < 4096) {
            unsigned long long key =
                ((unsigned long long)__float_as_uint(v) << 32) |
                (unsigned long long)(0xFFFFFFFFu - (unsigned)i);   // ties: lower idx first
            g_cand[p] = key;
        }
    }
}

// ---------------- stage 2: histogram select (warp-shfl scan) + bitonic + coords ----
__global__ void k_topk_sel(const float* __restrict__ heat) {
    __shared__ unsigned long long sbuf[4096];   // aliased as 8192-bin u32 histogram
    __shared__ int wtot[32];
    __shared__ int sB, sTot, sPos, sAll;
    unsigned int* hist = (unsigned int*)sbuf;
    int t = threadIdx.x;
    int lane = t & 31, wid = t >> 5;
    int cc = g_ctrs[0];
    if (cc > 4096) cc = 4096;

    #pragma unroll
    for (int q = 0; q < 8; q++) hist[q * 1024 + t] = 0u;
    if (t == 0) { sPos = 0; sB = 0; sTot = 0; sAll = 0; }
    __syncthreads();

    unsigned long long kk[4];
    #pragma unroll
    for (int q = 0; q < 4; q++) {
        int idx = q * 1024 + t;
        unsigned long long key = (idx < cc) ? g_cand[idx] : 0ULL;
        kk[q] = key;
        if (key >> 32)
            atomicAdd(&hist[(int)((key >> 50) & 0x1FFF)], 1u);
    }
    __syncthreads();

    // suffix-sum over thread groups (8 bins each) via warp shfl
    int gs = 0;
    #pragma unroll
    for (int b = 0; b < 8; b++) gs += hist[t * 8 + b];
    int s = gs;
    #pragma unroll
    for (int o = 1; o < 32; o <<= 1) {
        int v = __shfl_down_sync(0xFFFFFFFFu, s, o);
        if (lane + o < 32) s += v;
    }
    if (lane == 0) wtot[wid] = s;          // warp-inclusive suffix (from its own lane 0)
    __syncthreads();
    if (wid == 0) {
        int s2 = wtot[lane];
        #pragma unroll
        for (int o = 1; o < 32; o <<= 1) {
            int v = __shfl_down_sync(0xFFFFFFFFu, s2, o);
            if (lane + o < 32) s2 += v;
        }
        wtot[lane] = s2;                   // inclusive suffix over warps
        if (lane == 0) sAll = s2;
    }
    __syncthreads();
    int wsufExcl = (wid < 31) ? wtot[wid + 1] : 0;
    int suf  = s + wsufExcl;               // candidates in groups >= t
    int sufN = suf - gs;                   // candidates in groups >  t
    if (t == 0 && sAll < KJ) { sB = 0; sTot = sAll; }
    if (suf >= KJ && sufN < KJ) {
        int run = sufN;
        for (int b = t * 8 + 7; b >= t * 8; b--) {
            run += hist[b];
            if (run >= KJ) { sB = b; sTot = run; break; }
        }
    }
    __syncthreads();
    int B = sB, total = sTot;

    #pragma unroll
    for (int q = 0; q < 4; q++) {
        unsigned long long key = kk[q];
        if ((key >> 32) && (int)((key >> 50) & 0x1FFF) >= B) {
            int p = atomicAdd(&sPos, 1);
            sbuf[p] = key;
        }
    }
    __syncthreads();

    int n = (total <= 512) ? 512 : (total <= 1024) ? 1024 : (total <= 2048) ? 2048 : 4096;
    for (int i = total + t; i < n; i += 1024) sbuf[i] = 0ULL;
    __syncthreads();

    for (int k = 2; k <= n; k <<= 1) {
        for (int j = k >> 1; j > 0; j >>= 1) {
            for (int i = t; i < n; i += 1024) {
                int ixj = i ^ j;
                if (ixj > i) {
                    unsigned long long a = sbuf[i], b = sbuf[ixj];
                    bool descSeg = (i & k) == 0;
                    if (descSeg ? (a < b) : (a > b)) { sbuf[i] = b; sbuf[ixj] = a; }
                }
            }
            __syncthreads();
        }
    }

    if (t < KJ) {
        unsigned long long key = sbuf[t];
        float v = __uint_as_float((unsigned)(key >> 32));
        if (v > 0.008f) {
            unsigned pix = 0xFFFFFFFFu - (unsigned)(key & 0xFFFFFFFFu);
            float x = (float)(pix & 127u), y = (float)(pix >> 7);
            g_junc[2 * t + 0] = x + sigm(heat[7 * HW + pix]);
            g_junc[2 * t + 1] = y + sigm(heat[8 * HW + pix]);
        } else {
            g_junc[2 * t + 0] = 1e6f;
            g_junc[2 * t + 1] = 1e6f;
        }
    }
}

// ---------------- stage 3: HAFM decode + junction matching + id bitmap ----------------
__global__ void k_match(const float* __restrict__ heat) {
    __shared__ float sj[2 * KJ];
    for (int i = threadIdx.x; i < 2 * KJ; i += blockDim.x) sj[i] = g_junc[i];
    __syncthreads();
    int n = blockIdx.x * blockDim.x + threadIdx.x;
    if (n >= NLINES) return;
    int ch = n >> 14;
    int pix = n & (HW - 1);
    float x0 = (float)(pix & 127), y0 = (float)(pix >> 7);
    float a0   = sigm(heat[0 * HW + pix]);
    float a1   = sigm(heat[1 * HW + pix]);
    float a2   = sigm(heat[2 * HW + pix]);
    float dist = sigm(heat[3 * HW + pix]);
    float bias = sigm(heat[4 * HW + pix]);
    float d = dist + bias * (float)(ch - 1);
    d = fminf(fmaxf(d, 0.0f), 1.0f);
    float ang0 = (a0 - 0.5f) * PI_F * 2.0f;
    float c0 = cosf(ang0), s0 = sinf(ang0);
    float t1 =  tanf(a1 * (PI_F * 0.5f));
    float t2 = -tanf(a2 * (PI_F * 0.5f));
    float e1x = fminf(fmaxf((c0 - s0 * t1) * d * 5.0f + x0, 0.0f), 127.0f);
    float e1y = fminf(fmaxf((s0 + c0 * t1) * d * 5.0f + y0, 0.0f), 127.0f);
    float e2x = fminf(fmaxf((c0 - s0 * t2) * d * 5.0f + x0, 0.0f), 127.0f);
    float e2y = fminf(fmaxf((s0 + c0 * t2) * d * 5.0f + y0, 0.0f), 127.0f);

    int j1 = 0, j2 = 0;
    float m1 = 3.4e38f, m2 = 3.4e38f;
    const float2* sj2 = (const float2*)sj;
    #pragma unroll 4
    for (int k = 0; k < KJ; k++) {
        float2 jxy = sj2[k];
        float dx = jxy.x - e1x, dy = jxy.y - e1y;
        float dd = dx * dx + dy * dy;
        if (dd < m1) { m1 = dd; j1 = k; }
        dx = jxy.x - e2x; dy = jxy.y - e2y;
        dd = dx * dx + dy * dy;
        if (dd < m2) { m2 = dd; j2 = k; }
    }
    int lo = min(j1, j2), hi = max(j1, j2);
    if (lo < hi) {
        int id = lo * KJ + hi;
        atomicOr(&g_bitmap[id >> 5], 1u << (id & 31));
    }
}

// ---------------- stage 4: ordered bitmap compaction (warp-scan) ----------------
__global__ void k_compact(float* __restrict__ dout) {
    __shared__ int wsum[32];
    int tid = threadIdx.x;
    int lane = tid & 31, wid = tid >> 5;
    int base = tid * 3;
    unsigned w[3] = {0u, 0u, 0u};
    int c = 0;
    #pragma unroll
    for (int q = 0; q < 3; q++) {
        int wi = base + q;
        if (wi < NBMW) { w[q] = g_bitmap[wi]; c += __popc(w[q]); }
    }
    int incl = c;
    #pragma unroll
    for (int o = 1; o < 32; o <<= 1) {
        int v = __shfl_up_sync(0xFFFFFFFFu, incl, o);
        if (lane >= o) incl += v;
    }
    if (lane == 31) wsum[wid] = incl;
    __syncthreads();
    if (wid == 0) {
        int s = wsum[lane];
        #pragma unroll
        for (int o = 1; o < 32; o <<= 1) {
            int v = __shfl_up_sync(0xFFFFFFFFu, s, o);
            if (lane >= o) s += v;
        }
        wsum[lane] = s;
    }
    __syncthreads();
    int pos = (wid ? wsum[wid - 1] : 0) + incl - c;   // exclusive prefix
    #pragma unroll
    for (int q = 0; q < 3; q++) {
        unsigned ww = w[q];
        int wbase = (base + q) * 32;
        while (ww) {
            int b = __ffs(ww) - 1;
            ww &= ww - 1;
            int id = wbase + b;
            int lo = id / KJ, hi = id - lo * KJ;
            dout[pos * 4 + 0] = g_junc[2 * lo + 0];
            dout[pos * 4 + 1] = g_junc[2 * lo + 1];
            dout[pos * 4 + 2] = g_junc[2 * hi + 0];
            dout[pos * 4 + 3] = g_junc[2 * hi + 1];
            pos++;
        }
    }
    if (tid == 1023) g_ctrs[1] = wsum[31];
}

// ---------------- stage 5: LOI GEMM via tf32 MMA -> fp16 output ----------
__global__ void __launch_bounds__(256, 2)
k_loi_mma(const float* __restrict__ feat, const float* __restrict__ fc1w,
          const float* __restrict__ fc1b) {
    __shared__ float As[128][33];
    __shared__ float Bs[128][33];

    int tid  = threadIdx.x;
    int lane = tid & 31, wid = tid >> 5;
    int wm = (wid >> 2) * 64;
    int wn = (wid & 3) * 32;
    int g  = lane >> 2, tg = lane & 3;
    int p0 = blockIdx.x * 128;

    float c[4][4][4];
    #pragma unroll
    for (int mi = 0; mi < 4; mi++)
        #pragma unroll
        for (int ni = 0; ni < 4; ni++)
            #pragma unroll
            for (int r = 0; r < 4; r++) c[mi][ni][r] = 0.0f;

    for (int c0 = 0; c0 < 256; c0 += 32) {
        #pragma unroll
        for (int q = 0; q < 16; q++) {
            int f = tid + q * 256;
            int kc = f >> 7, p = f & 127;
            As[p][kc] = feat[(size_t)(c0 + kc) * HW + p0 + p];
        }
        #pragma unroll
        for (int q = 0; q < 16; q++) {
            int f = tid + q * 256;
            int cc = f & 31, o = f >> 5;
            Bs[o][cc] = fc1w[(size_t)o * 256 + c0 + cc];
        }
        __syncthreads();
        #pragma unroll
        for (int kk = 0; kk < 32; kk += 8) {
            unsigned a[4][4], b[4][2];
            #pragma unroll
            for (int mi = 0; mi < 4; mi++) {
                int r0 = wm + mi * 16 + g;
                a[mi][0] = __float_as_uint(As[r0][kk + tg]);
                a[mi][1] = __float_as_uint(As[r0 + 8][kk + tg]);
                a[mi][2] = __float_as_uint(As[r0][kk + tg + 4]);
                a[mi][3] = __float_as_uint(As[r0 + 8][kk + tg + 4]);
            }
            #pragma unroll
            for (int ni = 0; ni < 4; ni++) {
                int n0 = wn + ni * 8 + g;
                b[ni][0] = __float_as_uint(Bs[n0][kk + tg]);
                b[ni][1] = __float_as_uint(Bs[n0][kk + tg + 4]);
            }
            #pragma unroll
            for (int mi = 0; mi < 4; mi++)
                #pragma unroll
                for (int ni = 0; ni < 4; ni++)
                    asm volatile(
                        "mma.sync.aligned.m16n8k8.row.col.f32.tf32.tf32.f32 "
                        "{%0,%1,%2,%3}, {%4,%5,%6,%7}, {%8,%9}, {%0,%1,%2,%3};"
                        : "+f"(c[mi][ni][0]), "+f"(c[mi][ni][1]),
                          "+f"(c[mi][ni][2]), "+f"(c[mi][ni][3])
                        : "r"(a[mi][0]), "r"(a[mi][1]), "r"(a[mi][2]), "r"(a[mi][3]),
                          "r"(b[ni][0]), "r"(b[ni][1]));
        }
        __syncthreads();
    }

    #pragma unroll
    for (int mi = 0; mi < 4; mi++) {
        int p = p0 + wm + mi * 16 + g;
        #pragma unroll
        for (int ni = 0; ni < 4; ni++) {
            int o = wn + ni * 8 + 2 * tg;
            float bv0 = fc1b[o], bv1 = fc1b[o + 1];
            *(__half2*)&g_loi[(size_t)p * 128 + o] =
                __floats2half2_rn(c[mi][ni][0] + bv0, c[mi][ni][1] + bv1);
            *(__half2*)&g_loi[(size_t)(p + 8) * 128 + o] =
                __floats2half2_rn(c[mi][ni][2] + bv0, c[mi][ni][3] + bv1);
        }
    }
}

// ---------------- stage 6: bilinear sampling + maxpool4 -> feats[m][1024] fp16 --------
__global__ void k_sample(const float* __restrict__ dout) {
    int M = g_ctrs[1];
    int ch = threadIdx.x;      // 128 threads, one channel each
    for (int m = blockIdx.x; m < M; m += gridDim.x) {
        float x1 = dout[m * 4 + 0], y1 = dout[m * 4 + 1];
        float x2 = dout[m * 4 + 2], y2 = dout[m * 4 + 3];
        float mx = -3.4e38f;
        #pragma unroll 4
        for (int s = 0; s < 32; s++) {
            float t = (float)s / 31.0f;
            float px = x1 * t + x2 * (1.0f - t);
            float py = y1 * t + y2 * (1.0f - t);
            px = fminf(fmaxf(px, 0.0f), 127.0f);
            py = fminf(fmaxf(py, 0.0f), 127.0f);
            float fx0 = floorf(px), fy0 = floorf(py);
            int ix0 = (int)fx0, iy0 = (int)fy0;
            int ix1 = min(ix0 + 1, 127), iy1 = min(iy0 + 1, 127);
            float wx = px - fx0, wy = py - fy0;
            float v00 = __half2float(g_loi[(size_t)(iy0 * 128 + ix0) * 128 + ch]);
            float v01 = __half2float(g_loi[(size_t)(iy0 * 128 + ix1) * 128 + ch]);
            float v10 = __half2float(g_loi[(size_t)(iy1 * 128 + ix0) * 128 + ch]);
            float v11 = __half2float(g_loi[(size_t)(iy1 * 128 + ix1) * 128 + ch]);
            float v = v00 * (1.0f - wx) * (1.0f - wy) + v01 * wx * (1.0f - wy)
                    + v10 * (1.0f - wx) * wy + v11 * wx * wy;
            mx = ((s & 3) == 0) ? v : fmaxf(mx, v);
            if ((s & 3) == 3) g_bufA[(size_t)m * 1024 + ch * 8 + (s >> 2)] = __float2half(mx);
        }
    }
}

// ---------------- stage 7: persistent MLP GEMM, fp16 m16n8k16, 2-stage cp.async ------
__global__ void __launch_bounds__(256, 2)
k_mlp_mma(const __half* __restrict__ A, const __half* __restrict__ Wm,
          const float* __restrict__ bias, __half* __restrict__ Out) {
    __shared__ __align__(16) __half As[2][128][40];   // 80B row stride: conflict-free
    __shared__ __align__(16) __half Bs[2][128][40];

    int M = g_ctrs[1];
    int tiles = ((M + 127) >> 7) * 8;
    int tid  = threadIdx.x;
    int lane = tid & 31, wid = tid >> 5;
    int wm = (wid >> 2) * 64;
    int wn = (wid & 3) * 32;
    int g  = lane >> 2, tg = lane & 3;

    for (int tile = blockIdx.x; tile < tiles; tile += gridDim.x) {
        int mt = tile >> 3, ot = tile & 7;
        const __half* Aptr = A  + (size_t)(mt * 128) * 1024;
        const __half* Bptr = Wm + (size_t)(ot * 128) * 1024;

        float c[4][4][4];
        #pragma unroll
        for (int mi = 0; mi < 4; mi++)
            #pragma unroll
            for (int ni = 0; ni < 4; ni++)
                #pragma unroll
                for (int r = 0; r < 4; r++) c[mi][ni][r] = 0.0f;

        // prologue: stages 0 (k0=0) and 1 (k0=32)
        #pragma unroll
        for (int st = 0; st < 2; st++) {
            int k0 = st * 32;
            #pragma unroll
            for (int q = 0; q < 2; q++) {
                int f = tid + q * 256;
                int row = f >> 2, ce = (f & 3) * 8;
                cp16(&As[st][row][ce], &Aptr[(size_t)row * 1024 + k0 + ce]);
                cp16(&Bs[st][row][ce], &Bptr[(size_t)row * 1024 + k0 + ce]);
            }
            cp_commit();
        }

        for (int kc = 0; kc < 32; kc++) {
            cp_wait1();
            __syncthreads();
            int st = kc & 1;
            #pragma unroll
            for (int kk = 0; kk < 32; kk += 16) {
                unsigned a[4][4], b[4][2];
                #pragma unroll
                for (int mi = 0; mi < 4; mi++) {
                    int r0 = wm + mi * 16 + g;
                    a[mi][0] = *(const unsigned*)&As[st][r0][kk + 2 * tg];
                    a[mi][1] = *(const unsigned*)&As[st][r0 + 8][kk + 2 * tg];
                    a[mi][2] = *(const unsigned*)&As[st][r0][kk + 2 * tg + 8];
                    a[mi][3] = *(const unsigned*)&As[st][r0 + 8][kk + 2 * tg + 8];
                }
                #pragma unroll
                for (int ni = 0; ni < 4; ni++) {
                    int n0 = wn + ni * 8 + g;
                    b[ni][0] = *(const unsigned*)&Bs[st][n0][kk + 2 * tg];
                    b[ni][1] = *(const unsigned*)&Bs[st][n0][kk + 2 * tg + 8];
                }
                #pragma unroll
                for (int mi = 0; mi < 4; mi++)
                    #pragma unroll
                    for (int ni = 0; ni < 4; ni++)
                        asm volatile(
                            "mma.sync.aligned.m16n8k16.row.col.f32.f16.f16.f32 "
                            "{%0,%1,%2,%3}, {%4,%5,%6,%7}, {%8,%9}, {%0,%1,%2,%3};"
                            : "+f"(c[mi][ni][0]), "+f"(c[mi][ni][1]),
                              "+f"(c[mi][ni][2]), "+f"(c[mi][ni][3])
                            : "r"(a[mi][0]), "r"(a[mi][1]), "r"(a[mi][2]), "r"(a[mi][3]),
                              "r"(b[ni][0]), "r"(b[ni][1]));
            }
            __syncthreads();
            if (kc < 30) {
                int k0 = (kc + 2) * 32;
                #pragma unroll
                for (int q = 0; q < 2; q++) {
                    int f = tid + q * 256;
                    int row = f >> 2, ce = (f & 3) * 8;
                    cp16(&As[st][row][ce], &Aptr[(size_t)row * 1024 + k0 + ce]);
                    cp16(&Bs[st][row][ce], &Bptr[(size_t)row * 1024 + k0 + ce]);
                }
                cp_commit();
            }
        }

        // epilogue: bias + relu -> fp16
        #pragma unroll
        for (int mi = 0; mi < 4; mi++) {
            int m0 = mt * 128 + wm + mi * 16 + g;
            #pragma unroll
            for (int ni = 0; ni < 4; ni++) {
                int o = ot * 128 + wn + ni * 8 + 2 * tg;
                float bv0 = bias[o], bv1 = bias[o + 1];
                if (m0 < M) {
                    *(__half2*)&Out[(size_t)m0 * 1024 + o] =
                        __floats2half2_rn(fmaxf(c[mi][ni][0] + bv0, 0.0f),
                                          fmaxf(c[mi][ni][1] + bv1, 0.0f));
                }
                if (m0 + 8 < M) {
                    *(__half2*)&Out[(size_t)(m0 + 8) * 1024 + o] =
                        __floats2half2_rn(fmaxf(c[mi][ni][2] + bv0, 0.0f),
                                          fmaxf(c[mi][ni][3] + bv1, 0.0f));
                }
            }
        }
    }
}

// ---------------- stage 8: final dot + sigmoid ----------------
__global__ void k_final(const __half* __restrict__ h2, const float* __restrict__ w3,
                        const float* __restrict__ b3, float* __restrict__ dout) {
    int M = g_ctrs[1];
    int gtid = blockIdx.x * blockDim.x + threadIdx.x;
    int warp = gtid >> 5;
    int lane = threadIdx.x & 31;
    int nwarps = (gridDim.x * blockDim.x) >> 5;
    for (int m = warp; m < M; m += nwarps) {
        float acc = 0.0f;
        #pragma unroll 8
        for (int c = lane; c < 1024; c += 32)
            acc += __half2float(h2[(size_t)m * 1024 + c]) * w3[c];
        #pragma unroll
        for (int o = 16; o > 0; o >>= 1) acc += __shfl_xor_sync(0xFFFFFFFFu, acc, o);
        if (lane == 0)
            dout[4 * NLINES + m] = 1.0f / (1.0f + expf(-(acc + b3[0])));
    }
}

// ---------------- launch ----------------
extern "C" void kernel_launch(void* const* d_in, const int* in_sizes, int n_in,
                              void* d_out, int out_size) {
    const float* features = (const float*)d_in[0];
    const float* heatmaps = (const float*)d_in[1];
    const float* fc1_w    = (const float*)d_in[2];
    const float* fc1_b    = (const float*)d_in[3];
    const float* w1       = (const float*)d_in[4];
    const float* b1       = (const float*)d_in[5];
    const float* w2       = (const float*)d_in[6];
    const float* b2       = (const float*)d_in[7];
    const float* w3       = (const float*)d_in[8];
    const float* b3       = (const float*)d_in[9];
    float* dout = (float*)d_out;

    static cudaStream_t s2 = nullptr;
    static cudaEvent_t evFork = nullptr, evJoin = nullptr;
    if (!s2) {
        cudaStreamCreateWithFlags(&s2, cudaStreamNonBlocking);
        cudaEventCreateWithFlags(&evFork, cudaEventDisableTiming);
        cudaEventCreateWithFlags(&evJoin, cudaEventDisableTiming);
    }

    void *p_ctrs, *p_bitmap;
    cudaGetSymbolAddress(&p_ctrs,   g_ctrs);
    cudaGetSymbolAddress(&p_bitmap, g_bitmap);
    (void)in_sizes; (void)n_in;

    cudaMemsetAsync(p_ctrs,   0, sizeof(int) * 2);
    cudaMemsetAsync(p_bitmap, 0, sizeof(unsigned int) * NBMW);
    cudaMemsetAsync(dout,     0, (size_t)out_size * sizeof(float));

    // fork: weight cvt + LOI GEMM on side stream, overlapping the front-end chain
    cudaEventRecord(evFork, 0);
    cudaStreamWaitEvent(s2, evFork, 0);
    k_cvt<<<4096, 256, 0, s2>>>(w1, w2);
    k_loi_mma<<<128, 256, 0, s2>>>(features, fc1_w, fc1_b);
    cudaEventRecord(evJoin, s2);

    k_prop<<<64, 256>>>(heatmaps);
    k_topk_sel<<<1, 1024>>>(heatmaps);
    k_match<<<192, 256>>>(heatmaps);
    k_compact<<<1, 1024>>>(dout);

    cudaStreamWaitEvent(0, evJoin, 0);
    k_sample<<<2048, 128>>>(dout);

    __half* A = nullptr; __half* B = nullptr; __half* W1 = nullptr; __half* W2 = nullptr;
    cudaGetSymbolAddress((void**)&A,  g_bufA);
    cudaGetSymbolAddress((void**)&B,  g_bufB);
    cudaGetSymbolAddress((void**)&W1, g_w1h);
    cudaGetSymbolAddress((void**)&W2, g_w2h);

    k_mlp_mma<<<296, 256>>>(A, W1, b1, B);
    k_mlp_mma<<<296, 256>>>(B, W2, b2, A);
    k_final<<<256, 128>>>(A, w3, b3, dout);
}